// round 1
// baseline (speedup 1.0000x reference)
#include <cuda_runtime.h>
#include <cstdint>
#include <cstddef>

// Problem constants
#define E_ 32
#define T_ 2048
#define H_ 1024
#define I_ 512
#define K_ 4
#define P_ (T_ * K_)   // 8192 (token, slot) pairs; every slot is a pair

// ---------------- scratch (device globals; no allocation allowed) ----------
__device__ float g_gu[(size_t)P_ * 2 * I_];   // 32 MB: gate_up outputs per pair
__device__ float g_h [(size_t)P_ * I_];       // 16 MB: silu(gate)*up per pair
__device__ int   g_tok[P_];
__device__ float g_wt [P_];
__device__ int   g_cnt[E_];
__device__ int   g_cur[E_];
__device__ int   g_offs[E_ + 1];

// ---------------- routing ----------------
__global__ void k_zero(float* __restrict__ out) {
    int i = blockIdx.x * blockDim.x + threadIdx.x;
    const int n = T_ * H_;
    for (; i < n; i += gridDim.x * blockDim.x) out[i] = 0.0f;
    if (blockIdx.x == 0 && threadIdx.x < E_) {
        g_cnt[threadIdx.x] = 0;
        g_cur[threadIdx.x] = 0;
    }
}

__global__ void k_count(const int* __restrict__ idx) {
    int p = blockIdx.x * blockDim.x + threadIdx.x;
    if (p < P_) atomicAdd(&g_cnt[idx[p]], 1);
}

__global__ void k_scan() {
    // trivial 32-entry exclusive scan, single thread
    int s = 0;
    for (int e = 0; e < E_; e++) { g_offs[e] = s; s += g_cnt[e]; }
    g_offs[E_] = s;  // == P_
}

__global__ void k_place(const int* __restrict__ idx, const float* __restrict__ w) {
    int p = blockIdx.x * blockDim.x + threadIdx.x;
    if (p < P_) {
        int e = idx[p];
        int pos = g_offs[e] + atomicAdd(&g_cur[e], 1);
        g_tok[pos] = p / K_;
        g_wt[pos]  = w[p];
    }
}

// ---------------- tiled fp32 GEMMs ----------------
#define BM 64
#define BN 64
#define BK 16

// GEMM1: for expert e, rows = gathered hidden rows of its pairs,
//        B = gate_up_proj[e] (2I x H), C -> g_gu (pair-major, 2I wide)
__global__ __launch_bounds__(256) void k_gemm1(const float* __restrict__ X,
                                               const float* __restrict__ Wg) {
    const int e    = blockIdx.z;
    const int base = g_offs[e];
    const int ne   = g_offs[e + 1] - base;
    const int mt   = blockIdx.y;
    if (mt * BM >= ne) return;
    const int nb = blockIdx.x;

    __shared__ float As[BK][BM + 4];
    __shared__ float Bs[BK][BN + 4];

    const int tid = threadIdx.x;
    const int tx  = tid & 15;
    const int ty  = tid >> 4;

    // load-role indices: each thread owns one float4 of A and one of B per k-tile
    const int lm = tid >> 2;          // 0..63 (row within tile)
    const int ks = (tid & 3) * 4;     // 0,4,8,12 (k offset)

    const int rowm = mt * BM + lm;
    const int rowp = base + (rowm < ne ? rowm : 0);
    const float* aptr = X + (size_t)g_tok[rowp] * H_;
    const float* bptr = Wg + (size_t)e * (2 * I_) * H_ + (size_t)(nb * BN + lm) * H_;

    float acc[4][4];
    #pragma unroll
    for (int i = 0; i < 4; i++)
        #pragma unroll
        for (int j = 0; j < 4; j++) acc[i][j] = 0.0f;

    for (int kk = 0; kk < H_; kk += BK) {
        float4 av = *(const float4*)(aptr + kk + ks);
        float4 bv = *(const float4*)(bptr + kk + ks);
        As[ks + 0][lm] = av.x; As[ks + 1][lm] = av.y;
        As[ks + 2][lm] = av.z; As[ks + 3][lm] = av.w;
        Bs[ks + 0][lm] = bv.x; Bs[ks + 1][lm] = bv.y;
        Bs[ks + 2][lm] = bv.z; Bs[ks + 3][lm] = bv.w;
        __syncthreads();
        #pragma unroll
        for (int k = 0; k < BK; k++) {
            float4 a4 = *(const float4*)&As[k][ty * 4];
            float4 b4 = *(const float4*)&Bs[k][tx * 4];
            float ar[4] = {a4.x, a4.y, a4.z, a4.w};
            float br[4] = {b4.x, b4.y, b4.z, b4.w};
            #pragma unroll
            for (int i = 0; i < 4; i++)
                #pragma unroll
                for (int j = 0; j < 4; j++)
                    acc[i][j] += ar[i] * br[j];
        }
        __syncthreads();
    }

    #pragma unroll
    for (int ii = 0; ii < 4; ii++) {
        int rm = mt * BM + ty * 4 + ii;
        if (rm < ne) {
            float* o = g_gu + (size_t)(base + rm) * (2 * I_) + nb * BN + tx * 4;
            float4 v = make_float4(acc[ii][0], acc[ii][1], acc[ii][2], acc[ii][3]);
            *(float4*)o = v;
        }
    }
}

// elementwise: h = silu(gate) * up
__global__ void k_act() {
    int i = blockIdx.x * blockDim.x + threadIdx.x;
    if (i < P_ * I_) {
        int p = i / I_;
        int c = i - p * I_;
        float g = g_gu[(size_t)p * (2 * I_) + c];
        float u = g_gu[(size_t)p * (2 * I_) + I_ + c];
        float s = g / (1.0f + __expf(-g));
        g_h[(size_t)p * I_ + c] = s * u;
    }
}

// GEMM2: rows = g_h pairs of expert e (K=I_), B = down_proj[e] (H x I),
//        weighted atomic scatter-add into out[token]
__global__ __launch_bounds__(256) void k_gemm2(const float* __restrict__ Wd,
                                               float* __restrict__ out) {
    const int e    = blockIdx.z;
    const int base = g_offs[e];
    const int ne   = g_offs[e + 1] - base;
    const int mt   = blockIdx.y;
    if (mt * BM >= ne) return;
    const int nb = blockIdx.x;

    __shared__ float As[BK][BM + 4];
    __shared__ float Bs[BK][BN + 4];

    const int tid = threadIdx.x;
    const int tx  = tid & 15;
    const int ty  = tid >> 4;

    const int lm = tid >> 2;
    const int ks = (tid & 3) * 4;

    const int rowm = mt * BM + lm;
    const int rowp = base + (rowm < ne ? rowm : 0);
    const float* aptr = g_h + (size_t)rowp * I_;
    const float* bptr = Wd + (size_t)e * H_ * I_ + (size_t)(nb * BN + lm) * I_;

    float acc[4][4];
    #pragma unroll
    for (int i = 0; i < 4; i++)
        #pragma unroll
        for (int j = 0; j < 4; j++) acc[i][j] = 0.0f;

    for (int kk = 0; kk < I_; kk += BK) {
        float4 av = *(const float4*)(aptr + kk + ks);
        float4 bv = *(const float4*)(bptr + kk + ks);
        As[ks + 0][lm] = av.x; As[ks + 1][lm] = av.y;
        As[ks + 2][lm] = av.z; As[ks + 3][lm] = av.w;
        Bs[ks + 0][lm] = bv.x; Bs[ks + 1][lm] = bv.y;
        Bs[ks + 2][lm] = bv.z; Bs[ks + 3][lm] = bv.w;
        __syncthreads();
        #pragma unroll
        for (int k = 0; k < BK; k++) {
            float4 a4 = *(const float4*)&As[k][ty * 4];
            float4 b4 = *(const float4*)&Bs[k][tx * 4];
            float ar[4] = {a4.x, a4.y, a4.z, a4.w};
            float br[4] = {b4.x, b4.y, b4.z, b4.w};
            #pragma unroll
            for (int i = 0; i < 4; i++)
                #pragma unroll
                for (int j = 0; j < 4; j++)
                    acc[i][j] += ar[i] * br[j];
        }
        __syncthreads();
    }

    #pragma unroll
    for (int ii = 0; ii < 4; ii++) {
        int rm = mt * BM + ty * 4 + ii;
        if (rm < ne) {
            int   t  = g_tok[base + rm];
            float wt = g_wt[base + rm];
            float* o = out + (size_t)t * H_ + nb * BN + tx * 4;
            #pragma unroll
            for (int jj = 0; jj < 4; jj++)
                atomicAdd(o + jj, wt * acc[ii][jj]);
        }
    }
}

// ---------------- launch ----------------
extern "C" void kernel_launch(void* const* d_in, const int* in_sizes, int n_in,
                              void* d_out, int out_size) {
    const float* X    = (const float*)d_in[0];  // hidden_states  [T, H]
    const int*   idx  = (const int*)  d_in[1];  // top_k_index    [T, K]
    const float* w    = (const float*)d_in[2];  // top_k_weights  [T, K]
    const float* gup  = (const float*)d_in[3];  // gate_up_proj   [E, 2I, H]
    const float* down = (const float*)d_in[4];  // down_proj      [E, H, I]
    float* out = (float*)d_out;                 // [T, H] fp32

    k_zero <<<512, 256>>>(out);
    k_count<<<P_ / 256, 256>>>(idx);
    k_scan <<<1, 1>>>();
    k_place<<<P_ / 256, 256>>>(idx, w);

    // GEMM1: n-tiles over 2I=1024 -> 16; m-tiles worst case T/BM=32; experts 32
    k_gemm1<<<dim3(2 * I_ / BN, T_ / BM, E_), 256>>>(X, gup);
    k_act  <<<(P_ * I_) / 256, 256>>>();
    // GEMM2: n-tiles over H=1024 -> 16
    k_gemm2<<<dim3(H_ / BN, T_ / BM, E_), 256>>>(down, out);
}

// round 4
// speedup vs baseline: 2.1906x; 2.1906x over previous
#include <cuda_runtime.h>
#include <cuda_bf16.h>
#include <cstdint>
#include <cstddef>

// Problem constants
#define E_ 32
#define T_ 2048
#define H_ 1024
#define I_ 512
#define K_ 4
#define P_ (T_ * K_)   // 8192 (token, slot) pairs

// tcgen05 only exists in arch-specific (sm_103a/sm_100a) compilation passes.
#if defined(__CUDA_ARCH_SPECIFIC__) || defined(__CUDA_ARCH_FEAT_SM103_ALL) || defined(__CUDA_ARCH_FEAT_SM100_ALL)
#define TC_OK 1
#else
#define TC_OK 0
#endif

// ---------------- scratch (device globals; no allocation allowed) ----------
__device__ __nv_bfloat16 g_xhi[(size_t)P_ * H_];
__device__ __nv_bfloat16 g_xlo[(size_t)P_ * H_];
__device__ __nv_bfloat16 g_wghi[(size_t)E_ * 2 * I_ * H_];
__device__ __nv_bfloat16 g_wglo[(size_t)E_ * 2 * I_ * H_];
__device__ __nv_bfloat16 g_wdhi[(size_t)E_ * H_ * I_];
__device__ __nv_bfloat16 g_wdlo[(size_t)E_ * H_ * I_];
__device__ __nv_bfloat16 g_hhi[(size_t)P_ * I_];
__device__ __nv_bfloat16 g_hlo[(size_t)P_ * I_];
__device__ int   g_tok[P_];
__device__ float g_wt [P_];
__device__ int   g_cnt[E_];
__device__ int   g_cur[E_];
__device__ int   g_offs[E_ + 1];

// ---------------- PTX helpers ----------------
__device__ __forceinline__ uint32_t smem_u32(const void* p) {
    uint32_t a;
    asm("{ .reg .u64 t; cvta.to.shared.u64 t, %1; cvt.u32.u64 %0, t; }" : "=r"(a) : "l"(p));
    return a;
}

#if TC_OK
__device__ __forceinline__ uint32_t elect1() {
    uint32_t p;
    asm volatile("{\n\t.reg .pred p;\n\telect.sync _|p, 0xFFFFFFFF;\n\tselp.b32 %0, 1, 0, p;\n\t}" : "=r"(p));
    return p;
}
__device__ __forceinline__ void mbar_init(uint32_t mbar, uint32_t cnt) {
    asm volatile("mbarrier.init.shared.b64 [%0], %1;" :: "r"(mbar), "r"(cnt) : "memory");
}
__device__ __forceinline__ void mbar_inval(uint32_t mbar) {
    asm volatile("mbarrier.inval.shared.b64 [%0];" :: "r"(mbar) : "memory");
}
__device__ __forceinline__ void mbar_wait(uint32_t mbar, uint32_t parity) {
    asm volatile(
        "{\n\t.reg .pred P;\n"
        "LW_%=:\n\t"
        "mbarrier.try_wait.parity.acquire.cta.shared::cta.b64 P, [%0], %1, 0x989680;\n\t"
        "@P bra LD_%=;\n\t"
        "bra LW_%=;\n"
        "LD_%=:\n\t}"
        :: "r"(mbar), "r"(parity) : "memory");
}
__device__ __forceinline__ void tm_alloc(uint32_t smem_dst, uint32_t ncols) {
    asm volatile("tcgen05.alloc.cta_group::1.sync.aligned.shared::cta.b32 [%0], %1;"
                 :: "r"(smem_dst), "r"(ncols) : "memory");
}
__device__ __forceinline__ void tm_dealloc(uint32_t tmem, uint32_t ncols) {
    asm volatile("tcgen05.dealloc.cta_group::1.sync.aligned.b32 %0, %1;" :: "r"(tmem), "r"(ncols));
}
__device__ __forceinline__ void tm_relinq() {
    asm volatile("tcgen05.relinquish_alloc_permit.cta_group::1.sync.aligned;");
}
__device__ __forceinline__ void mma_f16_ss(uint32_t d, uint64_t da, uint64_t db,
                                           uint32_t idesc, uint32_t en) {
    asm volatile(
        "{\n\t.reg .pred p;\n\tsetp.ne.u32 p, %4, 0;\n\t"
        "tcgen05.mma.cta_group::1.kind::f16 [%0], %1, %2, %3, {%5, %5, %5, %5}, p;\n\t}"
        :: "r"(d), "l"(da), "l"(db), "r"(idesc), "r"(en), "r"(0u) : "memory");
}
__device__ __forceinline__ void tm_commit(uint32_t mbar) {
    asm volatile("tcgen05.commit.cta_group::1.mbarrier::arrive::one.shared::cluster.b64 [%0];"
                 :: "r"(mbar) : "memory");
}
#define TM_FENCE_AFTER()  asm volatile("tcgen05.fence::after_thread_sync;" ::: "memory")
#define TM_FENCE_BEFORE() asm volatile("tcgen05.fence::before_thread_sync;" ::: "memory")
#define FENCE_ASYNC()     asm volatile("fence.proxy.async.shared::cta;" ::: "memory")
#define WAIT_LD()         asm volatile("tcgen05.wait::ld.sync.aligned;" ::: "memory")

#define LDTM_X32(r, addr) \
    asm volatile( \
        "tcgen05.ld.sync.aligned.32x32b.x32.b32 " \
        "{%0, %1, %2, %3, %4, %5, %6, %7, " \
        " %8, %9, %10, %11, %12, %13, %14, %15, " \
        " %16, %17, %18, %19, %20, %21, %22, %23, " \
        " %24, %25, %26, %27, %28, %29, %30, %31}, [%32];" \
        : "=r"((r)[0]),  "=r"((r)[1]),  "=r"((r)[2]),  "=r"((r)[3]), \
          "=r"((r)[4]),  "=r"((r)[5]),  "=r"((r)[6]),  "=r"((r)[7]), \
          "=r"((r)[8]),  "=r"((r)[9]),  "=r"((r)[10]), "=r"((r)[11]), \
          "=r"((r)[12]), "=r"((r)[13]), "=r"((r)[14]), "=r"((r)[15]), \
          "=r"((r)[16]), "=r"((r)[17]), "=r"((r)[18]), "=r"((r)[19]), \
          "=r"((r)[20]), "=r"((r)[21]), "=r"((r)[22]), "=r"((r)[23]), \
          "=r"((r)[24]), "=r"((r)[25]), "=r"((r)[26]), "=r"((r)[27]), \
          "=r"((r)[28]), "=r"((r)[29]), "=r"((r)[30]), "=r"((r)[31]) \
        : "r"(addr))

__device__ __forceinline__ uint64_t mk_desc(uint32_t a) {
    return 0x4000404000010000ULL | ((uint64_t)(a >> 4) & 0x3FFF);
}
// idesc: fp32 accum, bf16 A/B, M=128, N=128
#define IDESC_ ((1u << 4) | (1u << 7) | (1u << 10) | ((128u / 8) << 17) | ((128u / 16) << 24))
#endif  // TC_OK

#define SWZ(off) ((off) ^ (((off) >> 3) & 0x70))

// SMEM map (tc path): [0] tmem ptr, [16],[24] mbars, [1024 +) 2 stages x 64KB
#define STAGE_BYTES 65536
#define SMEM_TOT (1024 + 2 * STAGE_BYTES)

// ---------------- routing ----------------
__global__ void k_zero(float* __restrict__ out) {
    int i = blockIdx.x * blockDim.x + threadIdx.x;
    const int n = T_ * H_;
    for (; i < n; i += gridDim.x * blockDim.x) out[i] = 0.0f;
    if (blockIdx.x == 0 && threadIdx.x < E_) { g_cnt[threadIdx.x] = 0; g_cur[threadIdx.x] = 0; }
}
__global__ void k_count(const int* __restrict__ idx) {
    int p = blockIdx.x * blockDim.x + threadIdx.x;
    if (p < P_) atomicAdd(&g_cnt[idx[p]], 1);
}
__global__ void k_scan() {
    int s = 0;
    for (int e = 0; e < E_; e++) { g_offs[e] = s; s += g_cnt[e]; }
    g_offs[E_] = s;
}
__global__ void k_place(const int* __restrict__ idx, const float* __restrict__ w) {
    int p = blockIdx.x * blockDim.x + threadIdx.x;
    if (p < P_) {
        int e = idx[p];
        int pos = g_offs[e] + atomicAdd(&g_cur[e], 1);
        g_tok[pos] = p / K_;
        g_wt[pos]  = w[p];
    }
}

// ---------------- conversions ----------------
__device__ __forceinline__ void split4(float4 v, uint2& hi, uint2& lo) {
    __nv_bfloat16 h[4], l[4];
    float f[4] = {v.x, v.y, v.z, v.w};
    #pragma unroll
    for (int i = 0; i < 4; i++) {
        h[i] = __float2bfloat16(f[i]);
        l[i] = __float2bfloat16(f[i] - __bfloat162float(h[i]));
    }
    hi = *(uint2*)h; lo = *(uint2*)l;
}
__global__ void k_cvt_x(const float* __restrict__ X) {
    int p = blockIdx.x;
    int c = threadIdx.x * 4;
    float4 v = *(const float4*)(X + (size_t)g_tok[p] * H_ + c);
    uint2 hi, lo; split4(v, hi, lo);
    *(uint2*)(g_xhi + (size_t)p * H_ + c) = hi;
    *(uint2*)(g_xlo + (size_t)p * H_ + c) = lo;
}
__global__ void k_cvt_wg(const float* __restrict__ W) {
    size_t i = ((size_t)blockIdx.x * blockDim.x + threadIdx.x) * 4;
    float4 v = *(const float4*)(W + i);
    uint2 hi, lo; split4(v, hi, lo);
    *(uint2*)(g_wghi + i) = hi;
    *(uint2*)(g_wglo + i) = lo;
}
__global__ void k_cvt_wd(const float* __restrict__ W) {
    size_t i = ((size_t)blockIdx.x * blockDim.x + threadIdx.x) * 4;
    float4 v = *(const float4*)(W + i);
    uint2 hi, lo; split4(v, hi, lo);
    *(uint2*)(g_wdhi + i) = hi;
    *(uint2*)(g_wdlo + i) = lo;
}

__device__ __forceinline__ float rc(const __nv_bfloat16* hi, const __nv_bfloat16* lo, size_t i) {
    return __bfloat162float(hi[i]) + __bfloat162float(lo[i]);
}

// ---------------- GEMM 1: gu = Xg @ Wg^T, fused silu, emit h hi/lo ----------
// tiles: M=128 (pair rows), N=128 (64 gate cols + matching 64 up cols)
__global__ __launch_bounds__(256, 1)
void k_gemm1() {
    const int e    = blockIdx.z;
    const int base = g_offs[e];
    const int ne   = g_offs[e + 1] - base;
    const int mt   = blockIdx.y;
    if (mt * 128 >= ne) return;
    const int nb   = blockIdx.x;   // 0..7 over I_/64

    extern __shared__ char smem[];
    const int tid = threadIdx.x;

#if TC_OK
    const uint32_t sb32 = smem_u32(smem);
    const int wid = tid >> 5;
    const int lid = tid & 31;

    if (wid == 0) tm_alloc(sb32, 128);
    if (tid == 0) { mbar_init(sb32 + 16, 1); mbar_init(sb32 + 24, 1); }
    __syncthreads();
    uint32_t tmem;
    asm volatile("ld.shared.b32 %0, [%1];" : "=r"(tmem) : "r"(sb32));

    // per-thread load plan: 16 x 16B chunks (4 tiles x 128 rows x 8 chunks)
    const __nv_bfloat16* ptrs[16];
    int soff[16];
    #pragma unroll
    for (int t = 0; t < 16; t++) {
        int gid  = t * 256 + tid;
        int tile = gid >> 10;          // 0=Ahi 1=Alo 2=Bhi 3=Blo
        int row  = (gid >> 3) & 127;
        int ch   = gid & 7;
        const __nv_bfloat16* src;
        if (tile < 2) {
            int idx = mt * 128 + row;
            int r = base + (idx < ne ? idx : 0);
            src = (tile == 0 ? g_xhi : g_xlo) + (size_t)r * H_;
        } else {
            int n = (row < 64) ? (nb * 64 + row) : (I_ + nb * 64 + (row - 64));
            src = (tile == 2 ? g_wghi : g_wglo) + ((size_t)e * 2 * I_ + n) * H_;
        }
        ptrs[t] = src + ch * 8;
        soff[t] = tile * 16384 + SWZ(row * 128 + ch * 16);
    }

    auto do_load = [&](int s) {
        char* dst = smem + 1024 + s * STAGE_BYTES;
        #pragma unroll
        for (int t = 0; t < 16; t++) {
            *(uint4*)(dst + soff[t]) = *(const uint4*)ptrs[t];
            ptrs[t] += 64;
        }
    };

    const int KITERS = H_ / 64;  // 16
    do_load(0);
    FENCE_ASYNC();
    __syncthreads();

    int ph0 = 0, ph1 = 0;
    for (int it = 0; it < KITERS; it++) {
        const int cur = it & 1;
        if (wid == 0 && elect1()) {
            uint32_t sb = sb32 + 1024 + cur * STAGE_BYTES;
            uint64_t dah = mk_desc(sb), dal = mk_desc(sb + 16384);
            uint64_t dbh = mk_desc(sb + 32768), dbl = mk_desc(sb + 49152);
            #pragma unroll
            for (int p = 0; p < 3; p++) {
                uint64_t da = (p == 2) ? dal : dah;
                uint64_t db = (p == 1) ? dbl : dbh;
                #pragma unroll
                for (int ks = 0; ks < 4; ks++)
                    mma_f16_ss(tmem, da + ks * 2, db + ks * 2, IDESC_,
                               (it == 0 && p == 0 && ks == 0) ? 0u : 1u);
            }
            tm_commit(sb32 + 16 + cur * 8);
        }
        if (it + 1 < KITERS) {
            const int nxt = cur ^ 1;
            if (it >= 1) {
                if (nxt == 0) { mbar_wait(sb32 + 16, ph0); ph0 ^= 1; }
                else          { mbar_wait(sb32 + 24, ph1); ph1 ^= 1; }
            }
            do_load(nxt);
            FENCE_ASYNC();
            __syncthreads();
        }
    }
    mbar_wait(sb32 + 16, ph0);
    mbar_wait(sb32 + 24, ph1);
    TM_FENCE_AFTER();
    __syncthreads();

    if (wid < 4) {
        const int m = mt * 128 + wid * 32 + lid;
        const bool v = (m < ne);
        __nv_bfloat16* ohi = g_hhi + (size_t)(base + m) * I_ + nb * 64;
        __nv_bfloat16* olo = g_hlo + (size_t)(base + m) * I_ + nb * 64;
        #pragma unroll
        for (int half = 0; half < 2; half++) {
            uint32_t rg[32], ru[32];
            LDTM_X32(rg, tmem + half * 32);
            LDTM_X32(ru, tmem + 64 + half * 32);
            WAIT_LD();
            if (v) {
                #pragma unroll
                for (int c = 0; c < 32; c++) {
                    float gte = __uint_as_float(rg[c]);
                    float upv = __uint_as_float(ru[c]);
                    float hv  = (gte / (1.0f + __expf(-gte))) * upv;
                    __nv_bfloat16 hh = __float2bfloat16(hv);
                    __nv_bfloat16 hl = __float2bfloat16(hv - __bfloat162float(hh));
                    ohi[half * 32 + c] = hh;
                    olo[half * 32 + c] = hl;
                }
            }
        }
        TM_FENCE_BEFORE();
    }
    __syncthreads();
    if (tid == 0) { mbar_inval(sb32 + 16); mbar_inval(sb32 + 24); }
    if (wid == 0) { tm_relinq(); tm_dealloc(tmem, 128); }

#else  // ---------- SIMT fp32 fallback (compute_103 / sm_103 pass) ----------
    float* As = (float*)smem;                // [32][136]
    float* Bs = As + 32 * 136;               // [32][136]
    float* Cs = Bs + 32 * 136;               // [128][132]
    const int tx = tid & 15, ty = tid >> 4;

    float acc[8][8];
    #pragma unroll
    for (int i = 0; i < 8; i++)
        #pragma unroll
        for (int j = 0; j < 8; j++) acc[i][j] = 0.0f;

    for (int kk = 0; kk < H_; kk += 32) {
        for (int el = tid; el < 4096; el += 256) {
            int r = el >> 5, k = el & 31;
            int idx = mt * 128 + r;
            int rr = base + (idx < ne ? idx : 0);
            As[k * 136 + r] = rc(g_xhi, g_xlo, (size_t)rr * H_ + kk + k);
            int n = (r < 64) ? (nb * 64 + r) : (I_ + nb * 64 + (r - 64));
            Bs[k * 136 + r] = rc(g_wghi, g_wglo, ((size_t)e * 2 * I_ + n) * H_ + kk + k);
        }
        __syncthreads();
        #pragma unroll 8
        for (int k = 0; k < 32; k++) {
            float a[8], b[8];
            #pragma unroll
            for (int i = 0; i < 8; i++) a[i] = As[k * 136 + ty * 8 + i];
            #pragma unroll
            for (int j = 0; j < 8; j++) b[j] = Bs[k * 136 + tx * 8 + j];
            #pragma unroll
            for (int i = 0; i < 8; i++)
                #pragma unroll
                for (int j = 0; j < 8; j++) acc[i][j] += a[i] * b[j];
        }
        __syncthreads();
    }
    #pragma unroll
    for (int i = 0; i < 8; i++)
        #pragma unroll
        for (int j = 0; j < 8; j++)
            Cs[(ty * 8 + i) * 132 + tx * 8 + j] = acc[i][j];
    __syncthreads();
    for (int el = tid; el < 8192; el += 256) {
        int m = el >> 6, c = el & 63;
        if (mt * 128 + m < ne) {
            float g = Cs[m * 132 + c], u = Cs[m * 132 + 64 + c];
            float hv = (g / (1.0f + __expf(-g))) * u;
            __nv_bfloat16 hh = __float2bfloat16(hv);
            __nv_bfloat16 hl = __float2bfloat16(hv - __bfloat162float(hh));
            size_t o = (size_t)(base + mt * 128 + m) * I_ + nb * 64 + c;
            g_hhi[o] = hh; g_hlo[o] = hl;
        }
    }
#endif
}

// ---------------- GEMM 2: out += wt * (h @ Wd^T) ----------------
__global__ __launch_bounds__(256, 1)
void k_gemm2(float* __restrict__ out) {
    const int e    = blockIdx.z;
    const int base = g_offs[e];
    const int ne   = g_offs[e + 1] - base;
    const int mt   = blockIdx.y;
    if (mt * 128 >= ne) return;
    const int nb   = blockIdx.x;   // 0..7 over H_/128

    extern __shared__ char smem[];
    const int tid = threadIdx.x;

#if TC_OK
    const uint32_t sb32 = smem_u32(smem);
    const int wid = tid >> 5;
    const int lid = tid & 31;

    if (wid == 0) tm_alloc(sb32, 128);
    if (tid == 0) { mbar_init(sb32 + 16, 1); mbar_init(sb32 + 24, 1); }
    __syncthreads();
    uint32_t tmem;
    asm volatile("ld.shared.b32 %0, [%1];" : "=r"(tmem) : "r"(sb32));

    const __nv_bfloat16* ptrs[16];
    int soff[16];
    #pragma unroll
    for (int t = 0; t < 16; t++) {
        int gid  = t * 256 + tid;
        int tile = gid >> 10;
        int row  = (gid >> 3) & 127;
        int ch   = gid & 7;
        const __nv_bfloat16* src;
        if (tile < 2) {
            int idx = mt * 128 + row;
            int r = base + (idx < ne ? idx : 0);
            src = (tile == 0 ? g_hhi : g_hlo) + (size_t)r * I_;
        } else {
            int n = nb * 128 + row;
            src = (tile == 2 ? g_wdhi : g_wdlo) + ((size_t)e * H_ + n) * I_;
        }
        ptrs[t] = src + ch * 8;
        soff[t] = tile * 16384 + SWZ(row * 128 + ch * 16);
    }

    auto do_load = [&](int s) {
        char* dst = smem + 1024 + s * STAGE_BYTES;
        #pragma unroll
        for (int t = 0; t < 16; t++) {
            *(uint4*)(dst + soff[t]) = *(const uint4*)ptrs[t];
            ptrs[t] += 64;
        }
    };

    const int KITERS = I_ / 64;  // 8
    do_load(0);
    FENCE_ASYNC();
    __syncthreads();

    int ph0 = 0, ph1 = 0;
    for (int it = 0; it < KITERS; it++) {
        const int cur = it & 1;
        if (wid == 0 && elect1()) {
            uint32_t sb = sb32 + 1024 + cur * STAGE_BYTES;
            uint64_t dah = mk_desc(sb), dal = mk_desc(sb + 16384);
            uint64_t dbh = mk_desc(sb + 32768), dbl = mk_desc(sb + 49152);
            #pragma unroll
            for (int p = 0; p < 3; p++) {
                uint64_t da = (p == 2) ? dal : dah;
                uint64_t db = (p == 1) ? dbl : dbh;
                #pragma unroll
                for (int ks = 0; ks < 4; ks++)
                    mma_f16_ss(tmem, da + ks * 2, db + ks * 2, IDESC_,
                               (it == 0 && p == 0 && ks == 0) ? 0u : 1u);
            }
            tm_commit(sb32 + 16 + cur * 8);
        }
        if (it + 1 < KITERS) {
            const int nxt = cur ^ 1;
            if (it >= 1) {
                if (nxt == 0) { mbar_wait(sb32 + 16, ph0); ph0 ^= 1; }
                else          { mbar_wait(sb32 + 24, ph1); ph1 ^= 1; }
            }
            do_load(nxt);
            FENCE_ASYNC();
            __syncthreads();
        }
    }
    mbar_wait(sb32 + 16, ph0);
    mbar_wait(sb32 + 24, ph1);
    TM_FENCE_AFTER();
    __syncthreads();

    if (wid < 4) {
        const int m = mt * 128 + wid * 32 + lid;
        const bool v = (m < ne);
        int   tok = 0; float wt = 0.0f;
        if (v) { tok = g_tok[base + m]; wt = g_wt[base + m]; }
        float* obase = out + (size_t)tok * H_ + nb * 128;
        #pragma unroll
        for (int ch = 0; ch < 4; ch++) {
            uint32_t r[32];
            LDTM_X32(r, tmem + ch * 32);
            WAIT_LD();
            if (v) {
                #pragma unroll
                for (int c = 0; c < 32; c++)
                    atomicAdd(obase + ch * 32 + c, wt * __uint_as_float(r[c]));
            }
        }
        TM_FENCE_BEFORE();
    }
    __syncthreads();
    if (tid == 0) { mbar_inval(sb32 + 16); mbar_inval(sb32 + 24); }
    if (wid == 0) { tm_relinq(); tm_dealloc(tmem, 128); }

#else  // ---------- SIMT fp32 fallback ----------
    float* As = (float*)smem;                // [32][136]
    float* Bs = As + 32 * 136;               // [32][136]
    const int tx = tid & 15, ty = tid >> 4;

    float acc[8][8];
    #pragma unroll
    for (int i = 0; i < 8; i++)
        #pragma unroll
        for (int j = 0; j < 8; j++) acc[i][j] = 0.0f;

    for (int kk = 0; kk < I_; kk += 32) {
        for (int el = tid; el < 4096; el += 256) {
            int r = el >> 5, k = el & 31;
            int idx = mt * 128 + r;
            int rr = base + (idx < ne ? idx : 0);
            As[k * 136 + r] = rc(g_hhi, g_hlo, (size_t)rr * I_ + kk + k);
            int n = nb * 128 + r;
            Bs[k * 136 + r] = rc(g_wdhi, g_wdlo, ((size_t)e * H_ + n) * I_ + kk + k);
        }
        __syncthreads();
        #pragma unroll 8
        for (int k = 0; k < 32; k++) {
            float a[8], b[8];
            #pragma unroll
            for (int i = 0; i < 8; i++) a[i] = As[k * 136 + ty * 8 + i];
            #pragma unroll
            for (int j = 0; j < 8; j++) b[j] = Bs[k * 136 + tx * 8 + j];
            #pragma unroll
            for (int i = 0; i < 8; i++)
                #pragma unroll
                for (int j = 0; j < 8; j++) acc[i][j] += a[i] * b[j];
        }
        __syncthreads();
    }
    #pragma unroll
    for (int i = 0; i < 8; i++) {
        int m = mt * 128 + ty * 8 + i;
        if (m < ne) {
            int   tok = g_tok[base + m];
            float wt  = g_wt[base + m];
            float* o  = out + (size_t)tok * H_ + nb * 128 + tx * 8;
            #pragma unroll
            for (int j = 0; j < 8; j++)
                atomicAdd(o + j, wt * acc[i][j]);
        }
    }
#endif
}

// ---------------- launch ----------------
extern "C" void kernel_launch(void* const* d_in, const int* in_sizes, int n_in,
                              void* d_out, int out_size) {
    const float* X    = (const float*)d_in[0];  // hidden_states  [T, H]
    const int*   idx  = (const int*)  d_in[1];  // top_k_index    [T, K]
    const float* w    = (const float*)d_in[2];  // top_k_weights  [T, K]
    const float* gup  = (const float*)d_in[3];  // gate_up_proj   [E, 2I, H]
    const float* down = (const float*)d_in[4];  // down_proj      [E, H, I]
    float* out = (float*)d_out;                 // [T, H] fp32

    static int attr_done = 0;
    if (!attr_done) {
        cudaFuncSetAttribute(k_gemm1, cudaFuncAttributeMaxDynamicSharedMemorySize, SMEM_TOT);
        cudaFuncSetAttribute(k_gemm2, cudaFuncAttributeMaxDynamicSharedMemorySize, SMEM_TOT);
        attr_done = 1;
    }

    k_zero  <<<512, 256>>>(out);
    k_count <<<P_ / 256, 256>>>(idx);
    k_scan  <<<1, 1>>>();
    k_place <<<P_ / 256, 256>>>(idx, w);

    k_cvt_x <<<P_, 256>>>(X);
    k_cvt_wg<<<(E_ * 2 * I_ * H_) / 1024, 256>>>(gup);
    k_cvt_wd<<<(E_ * H_ * I_) / 1024, 256>>>(down);

    k_gemm1<<<dim3(I_ / 64, T_ / 128, E_), 256, SMEM_TOT>>>();
    k_gemm2<<<dim3(H_ / 128, T_ / 128, E_), 256, SMEM_TOT>>>(out);
}

// round 6
// speedup vs baseline: 2.5380x; 1.1586x over previous
#include <cuda_runtime.h>
#include <cuda_bf16.h>
#include <cstdint>
#include <cstddef>

// Problem constants
#define E_ 32
#define T_ 2048
#define H_ 1024
#define I_ 512
#define K_ 4
#define P_ (T_ * K_)   // 8192 (token, slot) pairs

// tcgen05 only exists in arch-specific (sm_103a/sm_100a) compilation passes.
#if defined(__CUDA_ARCH_SPECIFIC__) || defined(__CUDA_ARCH_FEAT_SM103_ALL) || defined(__CUDA_ARCH_FEAT_SM100_ALL)
#define TC_OK 1
#else
#define TC_OK 0
#endif

// ---------------- scratch (device globals; no allocation allowed) ----------
__device__ __nv_bfloat16 g_xhi[(size_t)P_ * H_];
__device__ __nv_bfloat16 g_xlo[(size_t)P_ * H_];
__device__ __nv_bfloat16 g_hhi[(size_t)P_ * I_];
__device__ __nv_bfloat16 g_hlo[(size_t)P_ * I_];
__device__ int   g_tok[P_];
__device__ float g_wt [P_];
__device__ int   g_cnt[E_];
__device__ int   g_cur[E_];
__device__ int   g_offs[E_ + 1];

// ---------------- PTX helpers ----------------
__device__ __forceinline__ uint32_t smem_u32(const void* p) {
    uint32_t a;
    asm("{ .reg .u64 t; cvta.to.shared.u64 t, %1; cvt.u32.u64 %0, t; }" : "=r"(a) : "l"(p));
    return a;
}

#if TC_OK
__device__ __forceinline__ uint32_t elect1() {
    uint32_t p;
    asm volatile("{\n\t.reg .pred p;\n\telect.sync _|p, 0xFFFFFFFF;\n\tselp.b32 %0, 1, 0, p;\n\t}" : "=r"(p));
    return p;
}
__device__ __forceinline__ void mbar_init(uint32_t mbar, uint32_t cnt) {
    asm volatile("mbarrier.init.shared.b64 [%0], %1;" :: "r"(mbar), "r"(cnt) : "memory");
}
__device__ __forceinline__ void mbar_inval(uint32_t mbar) {
    asm volatile("mbarrier.inval.shared.b64 [%0];" :: "r"(mbar) : "memory");
}
__device__ __forceinline__ void mbar_wait(uint32_t mbar, uint32_t parity) {
    asm volatile(
        "{\n\t.reg .pred P;\n"
        "LW_%=:\n\t"
        "mbarrier.try_wait.parity.acquire.cta.shared::cta.b64 P, [%0], %1, 0x989680;\n\t"
        "@P bra LD_%=;\n\t"
        "bra LW_%=;\n"
        "LD_%=:\n\t}"
        :: "r"(mbar), "r"(parity) : "memory");
}
__device__ __forceinline__ void tm_alloc(uint32_t smem_dst, uint32_t ncols) {
    asm volatile("tcgen05.alloc.cta_group::1.sync.aligned.shared::cta.b32 [%0], %1;"
                 :: "r"(smem_dst), "r"(ncols) : "memory");
}
__device__ __forceinline__ void tm_dealloc(uint32_t tmem, uint32_t ncols) {
    asm volatile("tcgen05.dealloc.cta_group::1.sync.aligned.b32 %0, %1;" :: "r"(tmem), "r"(ncols));
}
__device__ __forceinline__ void tm_relinq() {
    asm volatile("tcgen05.relinquish_alloc_permit.cta_group::1.sync.aligned;");
}
__device__ __forceinline__ void mma_f16_ss(uint32_t d, uint64_t da, uint64_t db,
                                           uint32_t idesc, uint32_t en) {
    asm volatile(
        "{\n\t.reg .pred p;\n\tsetp.ne.u32 p, %4, 0;\n\t"
        "tcgen05.mma.cta_group::1.kind::f16 [%0], %1, %2, %3, {%5, %5, %5, %5}, p;\n\t}"
        :: "r"(d), "l"(da), "l"(db), "r"(idesc), "r"(en), "r"(0u) : "memory");
}
__device__ __forceinline__ void tm_commit(uint32_t mbar) {
    asm volatile("tcgen05.commit.cta_group::1.mbarrier::arrive::one.shared::cluster.b64 [%0];"
                 :: "r"(mbar) : "memory");
}
#define TM_FENCE_AFTER()  asm volatile("tcgen05.fence::after_thread_sync;" ::: "memory")
#define TM_FENCE_BEFORE() asm volatile("tcgen05.fence::before_thread_sync;" ::: "memory")
#define FENCE_ASYNC()     asm volatile("fence.proxy.async.shared::cta;" ::: "memory")
#define WAIT_LD()         asm volatile("tcgen05.wait::ld.sync.aligned;" ::: "memory")

#define LDTM_X32(r, addr) \
    asm volatile( \
        "tcgen05.ld.sync.aligned.32x32b.x32.b32 " \
        "{%0, %1, %2, %3, %4, %5, %6, %7, " \
        " %8, %9, %10, %11, %12, %13, %14, %15, " \
        " %16, %17, %18, %19, %20, %21, %22, %23, " \
        " %24, %25, %26, %27, %28, %29, %30, %31}, [%32];" \
        : "=r"((r)[0]),  "=r"((r)[1]),  "=r"((r)[2]),  "=r"((r)[3]), \
          "=r"((r)[4]),  "=r"((r)[5]),  "=r"((r)[6]),  "=r"((r)[7]), \
          "=r"((r)[8]),  "=r"((r)[9]),  "=r"((r)[10]), "=r"((r)[11]), \
          "=r"((r)[12]), "=r"((r)[13]), "=r"((r)[14]), "=r"((r)[15]), \
          "=r"((r)[16]), "=r"((r)[17]), "=r"((r)[18]), "=r"((r)[19]), \
          "=r"((r)[20]), "=r"((r)[21]), "=r"((r)[22]), "=r"((r)[23]), \
          "=r"((r)[24]), "=r"((r)[25]), "=r"((r)[26]), "=r"((r)[27]), \
          "=r"((r)[28]), "=r"((r)[29]), "=r"((r)[30]), "=r"((r)[31]) \
        : "r"(addr))

__device__ __forceinline__ uint64_t mk_desc(uint32_t a) {
    return 0x4000404000010000ULL | ((uint64_t)(a >> 4) & 0x3FFF);
}
// idesc: fp32 accum, bf16 A/B, M=128, N=128
#define IDESC_ ((1u << 4) | (1u << 7) | (1u << 10) | ((128u / 8) << 17) | ((128u / 16) << 24))
#endif  // TC_OK

#define SWZ(off) ((off) ^ (((off) >> 3) & 0x70))

// SMEM map (tc path): [0] tmem ptr, [16],[24] mbars, [1024 +) 2 stages x 64KB
// stage layout: Ahi 16K | Alo 16K | Bhi 16K | Blo 16K
#define STAGE_BYTES 65536
#define SMEM_TOT (1024 + 2 * STAGE_BYTES)

// ---------------- routing ----------------
__global__ void k_zero(float* __restrict__ out) {
    int i = blockIdx.x * blockDim.x + threadIdx.x;
    const int n = T_ * H_;
    for (; i < n; i += gridDim.x * blockDim.x) out[i] = 0.0f;
    if (blockIdx.x == 0 && threadIdx.x < E_) { g_cnt[threadIdx.x] = 0; g_cur[threadIdx.x] = 0; }
}
__global__ void k_count(const int* __restrict__ idx) {
    int p = blockIdx.x * blockDim.x + threadIdx.x;
    if (p < P_) atomicAdd(&g_cnt[idx[p]], 1);
}
__global__ void k_scan() {
    int s = 0;
    for (int e = 0; e < E_; e++) { g_offs[e] = s; s += g_cnt[e]; }
    g_offs[E_] = s;
}
__global__ void k_place(const int* __restrict__ idx, const float* __restrict__ w) {
    int p = blockIdx.x * blockDim.x + threadIdx.x;
    if (p < P_) {
        int e = idx[p];
        int pos = g_offs[e] + atomicAdd(&g_cur[e], 1);
        g_tok[pos] = p / K_;
        g_wt[pos]  = w[p];
    }
}

// ---------------- conversions ----------------
__device__ __forceinline__ void split4(float4 v, uint2& hi, uint2& lo) {
    __nv_bfloat16 h[4], l[4];
    float f[4] = {v.x, v.y, v.z, v.w};
    #pragma unroll
    for (int i = 0; i < 4; i++) {
        h[i] = __float2bfloat16(f[i]);
        l[i] = __float2bfloat16(f[i] - __bfloat162float(h[i]));
    }
    hi = *(uint2*)h; lo = *(uint2*)l;
}
// gather hidden rows into pair order + split
__global__ void k_cvt_x(const float* __restrict__ X) {
    int p = blockIdx.x;
    int c = threadIdx.x * 4;
    float4 v = *(const float4*)(X + (size_t)g_tok[p] * H_ + c);
    uint2 hi, lo; split4(v, hi, lo);
    *(uint2*)(g_xhi + (size_t)p * H_ + c) = hi;
    *(uint2*)(g_xlo + (size_t)p * H_ + c) = lo;
}

__device__ __forceinline__ float rc(const __nv_bfloat16* hi, const __nv_bfloat16* lo, size_t i) {
    return __bfloat162float(hi[i]) + __bfloat162float(lo[i]);
}

// ---------------- GEMM 1: gu = Xg @ Wg^T, fused silu, emit h hi/lo ----------
// tiles: M=128 (pair rows), N=128 (64 gate cols + matching 64 up cols)
// B (weights) loaded fp32 from gmem, split to bf16 hi/lo during SMEM fill.
__global__ __launch_bounds__(256, 1)
void k_gemm1(const float* __restrict__ gup) {
    const int e    = blockIdx.z;
    const int base = g_offs[e];
    const int ne   = g_offs[e + 1] - base;
    const int mt   = blockIdx.y;
    if (mt * 128 >= ne) return;
    const int nb   = blockIdx.x;   // 0..7 over I_/64

    extern __shared__ char smem[];
    const int tid = threadIdx.x;

#if TC_OK
    const uint32_t sb32 = smem_u32(smem);
    const int wid = tid >> 5;
    const int lid = tid & 31;

    if (wid == 0) tm_alloc(sb32, 128);
    if (tid == 0) { mbar_init(sb32 + 16, 1); mbar_init(sb32 + 24, 1); }
    __syncthreads();
    uint32_t tmem;
    asm volatile("ld.shared.b32 %0, [%1];" : "=r"(tmem) : "r"(sb32));

    // A plan: 8 x 16B chunks (2 tiles x 128 rows x 8 chunks of bf16)
    const __nv_bfloat16* aptr[8];
    int asoff[8];
    #pragma unroll
    for (int t = 0; t < 8; t++) {
        int gid  = t * 256 + tid;        // 0..2047
        int tile = gid >> 10;            // 0=hi 1=lo
        int row  = (gid >> 3) & 127;
        int ch   = gid & 7;
        int idx  = mt * 128 + row;
        int r    = base + (idx < ne ? idx : 0);
        aptr[t]  = (tile ? g_xlo : g_xhi) + (size_t)r * H_ + ch * 8;
        asoff[t] = tile * 16384 + SWZ(row * 128 + ch * 16);
    }
    // B plan: 8 x float4 fp32 loads (128 rows x 16 float4), split to hi/lo
    const float* bptr[8];
    int bsoff[8];
    #pragma unroll
    for (int t = 0; t < 8; t++) {
        int gid = t * 256 + tid;         // 0..2047
        int row = gid >> 4;
        int c4  = gid & 15;
        int n = (row < 64) ? (nb * 64 + row) : (I_ + nb * 64 + (row - 64));
        bptr[t]  = gup + ((size_t)e * 2 * I_ + n) * H_ + c4 * 4;
        bsoff[t] = SWZ(row * 128 + c4 * 8);
    }

    auto do_load = [&](int s) {
        char* dst = smem + 1024 + s * STAGE_BYTES;
        #pragma unroll
        for (int t = 0; t < 8; t++) {
            *(uint4*)(dst + asoff[t]) = *(const uint4*)aptr[t];
            aptr[t] += 64;
        }
        #pragma unroll
        for (int t = 0; t < 8; t++) {
            float4 v = *(const float4*)bptr[t];
            uint2 hi, lo; split4(v, hi, lo);
            *(uint2*)(dst + 32768 + bsoff[t]) = hi;
            *(uint2*)(dst + 49152 + bsoff[t]) = lo;
            bptr[t] += 64;
        }
    };

    const int KITERS = H_ / 64;  // 16
    do_load(0);
    FENCE_ASYNC();
    __syncthreads();

    int ph0 = 0, ph1 = 0;
    for (int it = 0; it < KITERS; it++) {
        const int cur = it & 1;
        if (wid == 0 && elect1()) {
            uint32_t sb = sb32 + 1024 + cur * STAGE_BYTES;
            uint64_t dah = mk_desc(sb), dal = mk_desc(sb + 16384);
            uint64_t dbh = mk_desc(sb + 32768), dbl = mk_desc(sb + 49152);
            #pragma unroll
            for (int p = 0; p < 3; p++) {
                uint64_t da = (p == 2) ? dal : dah;
                uint64_t db = (p == 1) ? dbl : dbh;
                #pragma unroll
                for (int ks = 0; ks < 4; ks++)
                    mma_f16_ss(tmem, da + ks * 2, db + ks * 2, IDESC_,
                               (it == 0 && p == 0 && ks == 0) ? 0u : 1u);
            }
            tm_commit(sb32 + 16 + cur * 8);
        }
        if (it + 1 < KITERS) {
            const int nxt = cur ^ 1;
            if (it >= 1) {
                if (nxt == 0) { mbar_wait(sb32 + 16, ph0); ph0 ^= 1; }
                else          { mbar_wait(sb32 + 24, ph1); ph1 ^= 1; }
            }
            do_load(nxt);
            FENCE_ASYNC();
            __syncthreads();
        }
    }
    mbar_wait(sb32 + 16, ph0);
    mbar_wait(sb32 + 24, ph1);
    TM_FENCE_AFTER();
    __syncthreads();

    if (wid < 4) {
        const int m = mt * 128 + wid * 32 + lid;
        const bool v = (m < ne);
        __nv_bfloat16* ohi = g_hhi + (size_t)(base + m) * I_ + nb * 64;
        __nv_bfloat16* olo = g_hlo + (size_t)(base + m) * I_ + nb * 64;
        #pragma unroll
        for (int half = 0; half < 2; half++) {
            uint32_t rg[32], ru[32];
            LDTM_X32(rg, tmem + half * 32);
            LDTM_X32(ru, tmem + 64 + half * 32);
            WAIT_LD();
            if (v) {
                #pragma unroll
                for (int c = 0; c < 32; c++) {
                    float gte = __uint_as_float(rg[c]);
                    float upv = __uint_as_float(ru[c]);
                    float hv  = (gte / (1.0f + __expf(-gte))) * upv;
                    __nv_bfloat16 hh = __float2bfloat16(hv);
                    __nv_bfloat16 hl = __float2bfloat16(hv - __bfloat162float(hh));
                    ohi[half * 32 + c] = hh;
                    olo[half * 32 + c] = hl;
                }
            }
        }
        TM_FENCE_BEFORE();
    }
    __syncthreads();
    if (tid == 0) { mbar_inval(sb32 + 16); mbar_inval(sb32 + 24); }
    if (wid == 0) { tm_relinq(); tm_dealloc(tmem, 128); }

#else  // ---------- SIMT fp32 fallback (compute_103 / sm_103 pass) ----------
    float* As = (float*)smem;                // [32][136]
    float* Bs = As + 32 * 136;               // [32][136]
    float* Cs = Bs + 32 * 136;               // [128][132]
    const int tx = tid & 15, ty = tid >> 4;

    float acc[8][8];
    #pragma unroll
    for (int i = 0; i < 8; i++)
        #pragma unroll
        for (int j = 0; j < 8; j++) acc[i][j] = 0.0f;

    for (int kk = 0; kk < H_; kk += 32) {
        for (int el = tid; el < 4096; el += 256) {
            int r = el >> 5, k = el & 31;
            int idx = mt * 128 + r;
            int rr = base + (idx < ne ? idx : 0);
            As[k * 136 + r] = rc(g_xhi, g_xlo, (size_t)rr * H_ + kk + k);
            int n = (r < 64) ? (nb * 64 + r) : (I_ + nb * 64 + (r - 64));
            Bs[k * 136 + r] = gup[((size_t)e * 2 * I_ + n) * H_ + kk + k];
        }
        __syncthreads();
        #pragma unroll 8
        for (int k = 0; k < 32; k++) {
            float a[8], b[8];
            #pragma unroll
            for (int i = 0; i < 8; i++) a[i] = As[k * 136 + ty * 8 + i];
            #pragma unroll
            for (int j = 0; j < 8; j++) b[j] = Bs[k * 136 + tx * 8 + j];
            #pragma unroll
            for (int i = 0; i < 8; i++)
                #pragma unroll
                for (int j = 0; j < 8; j++) acc[i][j] += a[i] * b[j];
        }
        __syncthreads();
    }
    #pragma unroll
    for (int i = 0; i < 8; i++)
        #pragma unroll
        for (int j = 0; j < 8; j++)
            Cs[(ty * 8 + i) * 132 + tx * 8 + j] = acc[i][j];
    __syncthreads();
    for (int el = tid; el < 8192; el += 256) {
        int m = el >> 6, c = el & 63;
        if (mt * 128 + m < ne) {
            float g = Cs[m * 132 + c], u = Cs[m * 132 + 64 + c];
            float hv = (g / (1.0f + __expf(-g))) * u;
            __nv_bfloat16 hh = __float2bfloat16(hv);
            __nv_bfloat16 hl = __float2bfloat16(hv - __bfloat162float(hh));
            size_t o = (size_t)(base + mt * 128 + m) * I_ + nb * 64 + c;
            g_hhi[o] = hh; g_hlo[o] = hl;
        }
    }
#endif
}

// ---------------- GEMM 2: out += wt * (h @ Wd^T) ----------------
__global__ __launch_bounds__(256, 1)
void k_gemm2(const float* __restrict__ down, float* __restrict__ out) {
    const int e    = blockIdx.z;
    const int base = g_offs[e];
    const int ne   = g_offs[e + 1] - base;
    const int mt   = blockIdx.y;
    if (mt * 128 >= ne) return;
    const int nb   = blockIdx.x;   // 0..7 over H_/128

    extern __shared__ char smem[];
    const int tid = threadIdx.x;

#if TC_OK
    const uint32_t sb32 = smem_u32(smem);
    const int wid = tid >> 5;
    const int lid = tid & 31;

    if (wid == 0) tm_alloc(sb32, 128);
    if (tid == 0) { mbar_init(sb32 + 16, 1); mbar_init(sb32 + 24, 1); }
    __syncthreads();
    uint32_t tmem;
    asm volatile("ld.shared.b32 %0, [%1];" : "=r"(tmem) : "r"(sb32));

    const __nv_bfloat16* aptr[8];
    int asoff[8];
    #pragma unroll
    for (int t = 0; t < 8; t++) {
        int gid  = t * 256 + tid;
        int tile = gid >> 10;
        int row  = (gid >> 3) & 127;
        int ch   = gid & 7;
        int idx  = mt * 128 + row;
        int r    = base + (idx < ne ? idx : 0);
        aptr[t]  = (tile ? g_hlo : g_hhi) + (size_t)r * I_ + ch * 8;
        asoff[t] = tile * 16384 + SWZ(row * 128 + ch * 16);
    }
    const float* bptr[8];
    int bsoff[8];
    #pragma unroll
    for (int t = 0; t < 8; t++) {
        int gid = t * 256 + tid;
        int row = gid >> 4;
        int c4  = gid & 15;
        int n   = nb * 128 + row;
        bptr[t]  = down + ((size_t)e * H_ + n) * I_ + c4 * 4;
        bsoff[t] = SWZ(row * 128 + c4 * 8);
    }

    auto do_load = [&](int s) {
        char* dst = smem + 1024 + s * STAGE_BYTES;
        #pragma unroll
        for (int t = 0; t < 8; t++) {
            *(uint4*)(dst + asoff[t]) = *(const uint4*)aptr[t];
            aptr[t] += 64;
        }
        #pragma unroll
        for (int t = 0; t < 8; t++) {
            float4 v = *(const float4*)bptr[t];
            uint2 hi, lo; split4(v, hi, lo);
            *(uint2*)(dst + 32768 + bsoff[t]) = hi;
            *(uint2*)(dst + 49152 + bsoff[t]) = lo;
            bptr[t] += 64;
        }
    };

    const int KITERS = I_ / 64;  // 8
    do_load(0);
    FENCE_ASYNC();
    __syncthreads();

    int ph0 = 0, ph1 = 0;
    for (int it = 0; it < KITERS; it++) {
        const int cur = it & 1;
        if (wid == 0 && elect1()) {
            uint32_t sb = sb32 + 1024 + cur * STAGE_BYTES;
            uint64_t dah = mk_desc(sb), dal = mk_desc(sb + 16384);
            uint64_t dbh = mk_desc(sb + 32768), dbl = mk_desc(sb + 49152);
            #pragma unroll
            for (int p = 0; p < 3; p++) {
                uint64_t da = (p == 2) ? dal : dah;
                uint64_t db = (p == 1) ? dbl : dbh;
                #pragma unroll
                for (int ks = 0; ks < 4; ks++)
                    mma_f16_ss(tmem, da + ks * 2, db + ks * 2, IDESC_,
                               (it == 0 && p == 0 && ks == 0) ? 0u : 1u);
            }
            tm_commit(sb32 + 16 + cur * 8);
        }
        if (it + 1 < KITERS) {
            const int nxt = cur ^ 1;
            if (it >= 1) {
                if (nxt == 0) { mbar_wait(sb32 + 16, ph0); ph0 ^= 1; }
                else          { mbar_wait(sb32 + 24, ph1); ph1 ^= 1; }
            }
            do_load(nxt);
            FENCE_ASYNC();
            __syncthreads();
        }
    }
    mbar_wait(sb32 + 16, ph0);
    mbar_wait(sb32 + 24, ph1);
    TM_FENCE_AFTER();
    __syncthreads();

    if (wid < 4) {
        const int m = mt * 128 + wid * 32 + lid;
        const bool v = (m < ne);
        int   tok = 0; float wt = 0.0f;
        if (v) { tok = g_tok[base + m]; wt = g_wt[base + m]; }
        float* obase = out + (size_t)tok * H_ + nb * 128;
        #pragma unroll
        for (int ch = 0; ch < 4; ch++) {
            uint32_t r[32];
            LDTM_X32(r, tmem + ch * 32);
            WAIT_LD();
            if (v) {
                #pragma unroll
                for (int c = 0; c < 32; c++)
                    atomicAdd(obase + ch * 32 + c, wt * __uint_as_float(r[c]));
            }
        }
        TM_FENCE_BEFORE();
    }
    __syncthreads();
    if (tid == 0) { mbar_inval(sb32 + 16); mbar_inval(sb32 + 24); }
    if (wid == 0) { tm_relinq(); tm_dealloc(tmem, 128); }

#else  // ---------- SIMT fp32 fallback ----------
    float* As = (float*)smem;                // [32][136]
    float* Bs = As + 32 * 136;               // [32][136]
    const int tx = tid & 15, ty = tid >> 4;

    float acc[8][8];
    #pragma unroll
    for (int i = 0; i < 8; i++)
        #pragma unroll
        for (int j = 0; j < 8; j++) acc[i][j] = 0.0f;

    for (int kk = 0; kk < I_; kk += 32) {
        for (int el = tid; el < 4096; el += 256) {
            int r = el >> 5, k = el & 31;
            int idx = mt * 128 + r;
            int rr = base + (idx < ne ? idx : 0);
            As[k * 136 + r] = rc(g_hhi, g_hlo, (size_t)rr * I_ + kk + k);
            int n = nb * 128 + r;
            Bs[k * 136 + r] = down[((size_t)e * H_ + n) * I_ + kk + k];
        }
        __syncthreads();
        #pragma unroll 8
        for (int k = 0; k < 32; k++) {
            float a[8], b[8];
            #pragma unroll
            for (int i = 0; i < 8; i++) a[i] = As[k * 136 + ty * 8 + i];
            #pragma unroll
            for (int j = 0; j < 8; j++) b[j] = Bs[k * 136 + tx * 8 + j];
            #pragma unroll
            for (int i = 0; i < 8; i++)
                #pragma unroll
                for (int j = 0; j < 8; j++) acc[i][j] += a[i] * b[j];
        }
        __syncthreads();
    }
    #pragma unroll
    for (int i = 0; i < 8; i++) {
        int m = mt * 128 + ty * 8 + i;
        if (m < ne) {
            int   tok = g_tok[base + m];
            float wt  = g_wt[base + m];
            float* o  = out + (size_t)tok * H_ + nb * 128 + tx * 8;
            #pragma unroll
            for (int j = 0; j < 8; j++)
                atomicAdd(o + j, wt * acc[i][j]);
        }
    }
#endif
}

// ---------------- launch ----------------
extern "C" void kernel_launch(void* const* d_in, const int* in_sizes, int n_in,
                              void* d_out, int out_size) {
    const float* X    = (const float*)d_in[0];  // hidden_states  [T, H]
    const int*   idx  = (const int*)  d_in[1];  // top_k_index    [T, K]
    const float* w    = (const float*)d_in[2];  // top_k_weights  [T, K]
    const float* gup  = (const float*)d_in[3];  // gate_up_proj   [E, 2I, H]
    const float* down = (const float*)d_in[4];  // down_proj      [E, H, I]
    float* out = (float*)d_out;                 // [T, H] fp32

    static int attr_done = 0;
    if (!attr_done) {
        cudaFuncSetAttribute(k_gemm1, cudaFuncAttributeMaxDynamicSharedMemorySize, SMEM_TOT);
        cudaFuncSetAttribute(k_gemm2, cudaFuncAttributeMaxDynamicSharedMemorySize, SMEM_TOT);
        attr_done = 1;
    }

    k_zero  <<<512, 256>>>(out);
    k_count <<<P_ / 256, 256>>>(idx);
    k_scan  <<<1, 1>>>();
    k_place <<<P_ / 256, 256>>>(idx, w);

    k_cvt_x <<<P_, 256>>>(X);

    k_gemm1<<<dim3(I_ / 64, T_ / 128, E_), 256, SMEM_TOT>>>(gup);
    k_gemm2<<<dim3(H_ / 128, T_ / 128, E_), 256, SMEM_TOT>>>(down, out);
}